// round 17
// baseline (speedup 1.0000x reference)
#include <cuda_runtime.h>
#include <cuda_bf16.h>
#include <math.h>
#include <string.h>

// ============================================================================
// MNIST_CNN2D_TWN forward pass. R14: conv1 ported to mma.sync bf16 hi/lo
// (M=576/img in 3 chunks of 192, N=32 oc, K=25->32 taps; x split hi/lo ONCE
// per CTA; ternary w1 prebaked bf16). conv2/fc1 keep the R10 mma versions.
// tcgen05 unusable (harness builds PTX at compute_103; ptxas rejects it).
// ============================================================================

#define NIMG 4096

// ---------------- mma.sync wrapper (sm_80+ PTX, safe on compute_103) --------
__device__ __forceinline__ void mma_bf16(float* d,
                                         unsigned a0, unsigned a1, unsigned a2, unsigned a3,
                                         unsigned b0, unsigned b1) {
    asm volatile(
        "mma.sync.aligned.m16n8k16.row.col.f32.bf16.bf16.f32 "
        "{%0,%1,%2,%3}, {%4,%5,%6,%7}, {%8,%9}, {%0,%1,%2,%3};"
        : "+f"(d[0]), "+f"(d[1]), "+f"(d[2]), "+f"(d[3])
        : "r"(a0), "r"(a1), "r"(a2), "r"(a3), "r"(b0), "r"(b1));
}

// ---------------- device scratch (static; no allocation) ----------------
__device__ __align__(16) __nv_bfloat16 g_q1bf[1024];  // [oc=32][tap=32] bf16 (pad 0)
__device__ __align__(16) __nv_bfloat16 g_q2bf[65536]; // [ic=32][oc=64][tap=32] bf16
__device__ __align__(16) __nv_bfloat16 g_qf1b[524288];// [512][1024] ternary bf16
__device__ float g_qf2[5120];                         // [10][512] ternary
__device__ float g_pool1[(size_t)NIMG * 32 * 144];    // raw pooled conv1 (pre-bn)
__device__ float g_pool2[(size_t)NIMG * 64 * 16];     // raw pooled conv2 (pre-bn)
__device__ float g_z[(size_t)NIMG * 512];             // fc1 pre-bn output
__device__ float g_sum1[32], g_sq1[32], g_a1[32], g_d1[32];
__device__ float g_sum2[64], g_sq2[64], g_a2[64], g_d2[64];
__device__ float g_sum3[512], g_sq3[512], g_a3[512], g_d3[512];
__device__ unsigned g_tmax[4];                        // maxabs bits (w1,w2,wf1,wf2)

// ---------------- stats zeroing ----------------
__global__ void zero_stats_kernel() {
    int i = threadIdx.x;
    if (i < 32) { g_sum1[i] = 0.f; g_sq1[i] = 0.f; }
    if (i < 64) { g_sum2[i] = 0.f; g_sq2[i] = 0.f; }
    if (i < 4)  { g_tmax[i] = 0u; }
    for (int j = i; j < 512; j += blockDim.x) { g_sum3[j] = 0.f; g_sq3[j] = 0.f; }
}

// ---------------- grid-wide maxabs reduction ----------------
__global__ void maxabs_kernel(const float* __restrict__ w, int n, int which) {
    __shared__ float red[8];
    int tid = threadIdx.x;
    float m = 0.f;
    for (int i = blockIdx.x * blockDim.x + tid; i < n; i += gridDim.x * blockDim.x)
        m = fmaxf(m, fabsf(w[i]));
    #pragma unroll
    for (int o = 16; o; o >>= 1) m = fmaxf(m, __shfl_xor_sync(0xffffffffu, m, o));
    if ((tid & 31) == 0) red[tid >> 5] = m;
    __syncthreads();
    if (tid < 32) {
        float v = (tid < (int)(blockDim.x >> 5)) ? red[tid] : 0.f;
        #pragma unroll
        for (int o = 4; o; o >>= 1) v = fmaxf(v, __shfl_xor_sync(0xffffffffu, v, o));
        if (tid == 0) atomicMax(&g_tmax[which], __float_as_uint(v));
    }
}

// which: 2 -> g_qf1b bf16, 3 -> g_qf2 f32
__global__ void quantize_kernel(const float* __restrict__ w, int n, int which) {
    float t = 0.05f * __uint_as_float(g_tmax[which]);
    int i = blockIdx.x * blockDim.x + threadIdx.x;
    if (i >= n) return;
    float v = w[i];
    float qv = (v > t ? 1.f : 0.f) - (v < -t ? 1.f : 0.f);
    if (which == 2) g_qf1b[i] = __float2bfloat16(qv);
    else            g_qf2[i] = qv;
}

// w1 [oc=32][25] -> g_q1bf[oc][tap32] bf16 (ternary, pad 0)
__global__ void quantize_w1_kernel(const float* __restrict__ w) {
    float t = 0.05f * __uint_as_float(g_tmax[0]);
    int idx = blockIdx.x * blockDim.x + threadIdx.x;
    if (idx >= 1024) return;
    int oc = idx >> 5, tap = idx & 31;
    float val = 0.f;
    if (tap < 25) {
        float wv = w[oc * 25 + tap];
        val = (wv > t ? 1.f : 0.f) - (wv < -t ? 1.f : 0.f);
    }
    g_q1bf[idx] = __float2bfloat16(val);
}

// w2 [oc=64][ic=32][5][5] -> g_q2bf[ic][oc][tap32] bf16 (ternary, pad 0)
__global__ void quantize_w2_kernel(const float* __restrict__ w) {
    float t = 0.05f * __uint_as_float(g_tmax[1]);
    int idx = blockIdx.x * blockDim.x + threadIdx.x;
    if (idx >= 65536) return;
    int ic = idx >> 11, oc = (idx >> 5) & 63, tap = idx & 31;
    float val = 0.f;
    if (tap < 25) {
        float wv = w[oc * 800 + ic * 25 + tap];
        val = (wv > t ? 1.f : 0.f) - (wv < -t ? 1.f : 0.f);
    }
    g_q2bf[idx] = __float2bfloat16(val);
}

// ---------------- bn affine finalize ----------------
__global__ void finalize_kernel(const float* __restrict__ gam,
                                const float* __restrict__ bet, int which) {
    const float* sum; const float* sq; float* a; float* d; int C; float inv;
    if (which == 0)      { sum = g_sum1; sq = g_sq1; a = g_a1; d = g_d1; C = 32;  inv = 1.f / 2359296.f; }
    else if (which == 1) { sum = g_sum2; sq = g_sq2; a = g_a2; d = g_d2; C = 64;  inv = 1.f / 262144.f;  }
    else                 { sum = g_sum3; sq = g_sq3; a = g_a3; d = g_d3; C = 512; inv = 1.f / 4096.f;    }
    int i = blockIdx.x * blockDim.x + threadIdx.x;
    if (i < C) {
        float m = sum[i] * inv;
        float v = sq[i] * inv - m * m;
        float ai = gam[i] / sqrtf(v + 1e-5f);
        a[i] = ai;
        d[i] = bet[i] - m * ai;
    }
}

// ---------------- conv1 on mma.sync: 1->32, 5x5, bias+stats+maxpool2 --------
// CTA = 1 image. M=576 positions in 3 chunks of 192 (8 conv-rows x 24 cols),
// N=32 oc, K=25->32 taps. x hi/lo split ONCE; per-chunk: build A -> MMA ->
// Ds -> bias+stats+pool. Warp grid 4m x 2n; warp tile 48x16 (3 m16 x 2 n8).
__global__ __launch_bounds__(256) void conv1_mma_kernel(const float* __restrict__ x,
                                                        const float* __restrict__ b1) {
    __shared__ unsigned short xh[784], xl[784];
    __shared__ __align__(16) unsigned char BsW[2560];    // 32 oc rows x 80B
    __shared__ __align__(16) unsigned char Abuf[30720];  // Ah 15360 | Al 15360; reused as Ds f32[192*33]
    __shared__ float ssum[32], ssq[32];
    float* Ds = (float*)Abuf;

    int n = blockIdx.x, tid = threadIdx.x, lane = tid & 31, w = tid >> 5;
    int g = lane >> 2, tig = lane & 3;
    if (tid < 32) { ssum[tid] = 0.f; ssq[tid] = 0.f; }

    // stage x hi/lo once
    for (int i = tid; i < 784; i += 256) {
        float v = x[(size_t)n * 784 + i];
        __nv_bfloat16 h = __float2bfloat16(v);
        float hf = __bfloat162float(h);
        __nv_bfloat16 l = __float2bfloat16(v - hf);
        unsigned short hb, lb;
        memcpy(&hb, &h, 2); memcpy(&lb, &l, 2);
        xh[i] = hb; xl[i] = lb;
    }
    // B fill once: g_q1bf flat [32][32] bf16 -> stride-80 rows
    if (tid < 128) {
        uint4 v = ((const uint4*)g_q1bf)[tid];
        *(uint4*)(BsW + (tid >> 2) * 80 + (tid & 3) * 16) = v;
    }

    int m_w = (w >> 1) * 48, n_w = (w & 1) * 16;
    float oc_ls = 0.f, oc_lq = 0.f;                     // stats: fixed oc per thread
    int s_oc = tid & 31, s_cell0 = tid >> 5;
    float bias = b1[s_oc];

    for (int chunk = 0; chunk < 3; chunk++) {
        __syncthreads();                                 // Ds consumers done / xh ready
        // --- build A chunk: rows p = y_local*24+px, taps 32 (25 valid) ---
        if (tid < 192) {
            int yl = tid / 24, px = tid - (tid / 24) * 24;
            int base = (chunk * 8 + yl) * 28 + px;
            unsigned hw[13], lw[13];
            #pragma unroll
            for (int j = 0; j < 12; j++) {
                const int t0 = 2 * j, t1 = t0 + 1;
                const int o0 = (t0 / 5) * 28 + (t0 % 5);
                const int o1 = (t1 / 5) * 28 + (t1 % 5);
                hw[j] = (unsigned)xh[base + o0] | ((unsigned)xh[base + o1] << 16);
                lw[j] = (unsigned)xl[base + o0] | ((unsigned)xl[base + o1] << 16);
            }
            hw[12] = (unsigned)xh[base + 116];           // tap 24 = (4,4); high half 0
            lw[12] = (unsigned)xl[base + 116];
            unsigned char* da = Abuf + tid * 80;
            *(uint4*)(da)      = make_uint4(hw[0], hw[1], hw[2], hw[3]);
            *(uint4*)(da + 16) = make_uint4(hw[4], hw[5], hw[6], hw[7]);
            *(uint4*)(da + 32) = make_uint4(hw[8], hw[9], hw[10], hw[11]);
            *(uint4*)(da + 48) = make_uint4(hw[12], 0u, 0u, 0u);
            unsigned char* dl = Abuf + 15360 + tid * 80;
            *(uint4*)(dl)      = make_uint4(lw[0], lw[1], lw[2], lw[3]);
            *(uint4*)(dl + 16) = make_uint4(lw[4], lw[5], lw[6], lw[7]);
            *(uint4*)(dl + 32) = make_uint4(lw[8], lw[9], lw[10], lw[11]);
            *(uint4*)(dl + 48) = make_uint4(lw[12], 0u, 0u, 0u);
        }
        __syncthreads();
        // --- MMA: 2ks x {hi,lo} x 3mt x 2nt ---
        float acc[3][2][4];
        #pragma unroll
        for (int mt = 0; mt < 3; mt++)
            #pragma unroll
            for (int nt = 0; nt < 2; nt++)
                #pragma unroll
                for (int q = 0; q < 4; q++) acc[mt][nt][q] = 0.f;
        #pragma unroll
        for (int ks = 0; ks < 2; ks++) {
            int kb = (ks * 16 + tig * 2) * 2;
            unsigned b0[2], b1v[2];
            #pragma unroll
            for (int nt = 0; nt < 2; nt++) {
                const unsigned char* bp = BsW + (n_w + nt * 8 + g) * 80 + kb;
                b0[nt]  = *(const unsigned*)bp;
                b1v[nt] = *(const unsigned*)(bp + 16);
            }
            #pragma unroll
            for (int var = 0; var < 2; var++) {
                const unsigned char* Ab = Abuf + var * 15360;
                #pragma unroll
                for (int mt = 0; mt < 3; mt++) {
                    const unsigned char* ap = Ab + (m_w + mt * 16 + g) * 80 + kb;
                    unsigned a0 = *(const unsigned*)ap;
                    unsigned a1 = *(const unsigned*)(ap + 8 * 80);
                    unsigned a2 = *(const unsigned*)(ap + 16);
                    unsigned a3 = *(const unsigned*)(ap + 8 * 80 + 16);
                    #pragma unroll
                    for (int nt = 0; nt < 2; nt++)
                        mma_bf16(acc[mt][nt], a0, a1, a2, a3, b0[nt], b1v[nt]);
                }
            }
        }
        __syncthreads();                                 // all warps done reading A
        // --- frags -> Ds[192][33] (reuses Abuf) ---
        #pragma unroll
        for (int mt = 0; mt < 3; mt++)
            #pragma unroll
            for (int nt = 0; nt < 2; nt++) {
                int r0 = m_w + mt * 16 + g, c0 = n_w + nt * 8 + tig * 2;
                Ds[r0 * 33 + c0]           = acc[mt][nt][0];
                Ds[r0 * 33 + c0 + 1]       = acc[mt][nt][1];
                Ds[(r0 + 8) * 33 + c0]     = acc[mt][nt][2];
                Ds[(r0 + 8) * 33 + c0 + 1] = acc[mt][nt][3];
            }
        __syncthreads();
        // --- bias + stats + maxpool: 48 pooled cells x 32 oc, 6 cells/thread ---
        #pragma unroll
        for (int j = 0; j < 6; j++) {
            int cell = s_cell0 + 8 * j;                  // 0..47
            int qy = cell / 12, qx = cell - qy * 12;
            int p00 = (2 * qy) * 24 + 2 * qx;
            float v0 = Ds[p00 * 33 + s_oc] + bias;
            float v1 = Ds[(p00 + 1) * 33 + s_oc] + bias;
            float v2 = Ds[(p00 + 24) * 33 + s_oc] + bias;
            float v3 = Ds[(p00 + 25) * 33 + s_oc] + bias;
            oc_ls += v0 + v1 + v2 + v3;
            oc_lq = fmaf(v0, v0, oc_lq); oc_lq = fmaf(v1, v1, oc_lq);
            oc_lq = fmaf(v2, v2, oc_lq); oc_lq = fmaf(v3, v3, oc_lq);
            float mx = fmaxf(fmaxf(v0, v1), fmaxf(v2, v3));
            g_pool1[((size_t)n * 32 + s_oc) * 144 + (chunk * 4 + qy) * 12 + qx] = mx;
        }
    }
    __syncthreads();
    atomicAdd(&ssum[s_oc], oc_ls);
    atomicAdd(&ssq[s_oc], oc_lq);
    __syncthreads();
    if (tid < 32) { atomicAdd(&g_sum1[tid], ssum[tid]); atomicAdd(&g_sq1[tid], ssq[tid]); }
}

// ---------------- conv2 on mma.sync (R10): pre-split hi/lo + double buffer --
#define C2_DSM 88576

__global__ __launch_bounds__(256) void conv2_mma_kernel(const float* __restrict__ b2) {
    extern __shared__ __align__(16) unsigned char dynsm[];
    float* ssum = (float*)dynsm;
    float* ssq  = (float*)(dynsm + 256);
    unsigned short* ishh = (unsigned short*)(dynsm + 512);
    unsigned short* ishl = (unsigned short*)(dynsm + 18944);
    float* Ds = (float*)(dynsm + 512);                 // reuse, stride 65

    int tid = threadIdx.x, lane = tid & 31, w = tid >> 5;
    int n0 = blockIdx.x * 2;
    if (tid < 64) { ssum[tid] = 0.f; ssq[tid] = 0.f; }

    {
        const float4* src = (const float4*)(g_pool1 + (size_t)n0 * 4608);
        for (int i = tid; i < 2304; i += 256) {
            int c = (i / 36) & 31;
            float a = g_a1[c], d = g_d1[c];
            float4 r = src[i];
            float v0 = fmaxf(fmaf(a, r.x, d), 0.f);
            float v1 = fmaxf(fmaf(a, r.y, d), 0.f);
            float v2 = fmaxf(fmaf(a, r.z, d), 0.f);
            float v3 = fmaxf(fmaf(a, r.w, d), 0.f);
            __nv_bfloat162 h01 = __floats2bfloat162_rn(v0, v1);
            __nv_bfloat162 h23 = __floats2bfloat162_rn(v2, v3);
            float2 f01 = __bfloat1622float2(h01);
            float2 f23 = __bfloat1622float2(h23);
            __nv_bfloat162 l01 = __floats2bfloat162_rn(v0 - f01.x, v1 - f01.y);
            __nv_bfloat162 l23 = __floats2bfloat162_rn(v2 - f23.x, v3 - f23.y);
            ((__nv_bfloat162*)ishh)[2 * i]     = h01;
            ((__nv_bfloat162*)ishh)[2 * i + 1] = h23;
            ((__nv_bfloat162*)ishl)[2 * i]     = l01;
            ((__nv_bfloat162*)ishl)[2 * i + 1] = l23;
        }
    }
    __syncthreads();

    int g = lane >> 2, tig = lane & 3;
    int m_w = (w >> 1) * 32, n_w = (w & 1) * 32;
    float acc[2][4][4];
    #pragma unroll
    for (int mt = 0; mt < 2; mt++)
        #pragma unroll
        for (int nt = 0; nt < 4; nt++)
            #pragma unroll
            for (int q = 0; q < 4; q++) acc[mt][nt][q] = 0.f;

    int arow = tid & 127, ahalf = tid >> 7;
    int aimg = arow >> 6, apos = arow & 63, ay = apos >> 3, ax = apos & 7;
    int abase0 = aimg * 4608 + ay * 12 + ax;

    for (int ic = 0; ic < 32; ic++) {
        unsigned boff = (unsigned)(ic & 1) * 25600u;
        unsigned char* Ahb = dynsm + 37376 + boff;
        unsigned char* Alb = Ahb + 10240;
        unsigned char* Bsb = Ahb + 20480;

        {
            uint4 v = ((const uint4*)(g_q2bf + ic * 2048))[tid];
            *(uint4*)(Bsb + (tid >> 2) * 80 + (tid & 3) * 16) = v;
        }
        {
            const unsigned short* ph = ishh + abase0 + ic * 144;
            const unsigned short* pl = ishl + abase0 + ic * 144;
            unsigned hw[8], lw[8];
            if (ahalf == 0) {
                #pragma unroll
                for (int j = 0; j < 8; j++) {
                    const int t0 = 2 * j, t1 = t0 + 1;
                    const int o0 = (t0 / 5) * 12 + t0 % 5;
                    const int o1 = (t1 / 5) * 12 + t1 % 5;
                    hw[j] = (unsigned)ph[o0] | ((unsigned)ph[o1] << 16);
                    lw[j] = (unsigned)pl[o0] | ((unsigned)pl[o1] << 16);
                }
            } else {
                #pragma unroll
                for (int j = 0; j < 8; j++) {
                    const int t0 = 16 + 2 * j, t1 = t0 + 1;
                    unsigned h0 = 0, h1 = 0, l0 = 0, l1 = 0;
                    if (t0 < 25) { const int o0 = (t0 / 5) * 12 + t0 % 5; h0 = ph[o0]; l0 = pl[o0]; }
                    if (t1 < 25) { const int o1 = (t1 / 5) * 12 + t1 % 5; h1 = ph[o1]; l1 = pl[o1]; }
                    hw[j] = h0 | (h1 << 16);
                    lw[j] = l0 | (l1 << 16);
                }
            }
            unsigned char* da = Ahb + arow * 80 + ahalf * 32;
            *(uint4*)da        = make_uint4(hw[0], hw[1], hw[2], hw[3]);
            *(uint4*)(da + 16) = make_uint4(hw[4], hw[5], hw[6], hw[7]);
            unsigned char* dl = Alb + arow * 80 + ahalf * 32;
            *(uint4*)dl        = make_uint4(lw[0], lw[1], lw[2], lw[3]);
            *(uint4*)(dl + 16) = make_uint4(lw[4], lw[5], lw[6], lw[7]);
        }
        __syncthreads();
        #pragma unroll
        for (int ks = 0; ks < 2; ks++) {
            int kb = (ks * 16 + tig * 2) * 2;
            unsigned b0[4], b1[4];
            #pragma unroll
            for (int nt = 0; nt < 4; nt++) {
                const unsigned char* bp = Bsb + (n_w + nt * 8 + g) * 80 + kb;
                b0[nt] = *(const unsigned*)bp;
                b1[nt] = *(const unsigned*)(bp + 16);
            }
            #pragma unroll
            for (int var = 0; var < 2; var++) {
                const unsigned char* Ab = var ? Alb : Ahb;
                #pragma unroll
                for (int mt = 0; mt < 2; mt++) {
                    const unsigned char* ap = Ab + (m_w + mt * 16 + g) * 80 + kb;
                    unsigned a0 = *(const unsigned*)ap;
                    unsigned a1 = *(const unsigned*)(ap + 8 * 80);
                    unsigned a2 = *(const unsigned*)(ap + 16);
                    unsigned a3 = *(const unsigned*)(ap + 8 * 80 + 16);
                    #pragma unroll
                    for (int nt = 0; nt < 4; nt++)
                        mma_bf16(acc[mt][nt], a0, a1, a2, a3, b0[nt], b1[nt]);
                }
            }
        }
    }
    __syncthreads();

    #pragma unroll
    for (int mt = 0; mt < 2; mt++)
        #pragma unroll
        for (int nt = 0; nt < 4; nt++) {
            int r0 = m_w + mt * 16 + g, c0 = n_w + nt * 8 + tig * 2;
            Ds[r0 * 65 + c0]           = acc[mt][nt][0];
            Ds[r0 * 65 + c0 + 1]       = acc[mt][nt][1];
            Ds[(r0 + 8) * 65 + c0]     = acc[mt][nt][2];
            Ds[(r0 + 8) * 65 + c0 + 1] = acc[mt][nt][3];
        }
    __syncthreads();

    if (tid < 128) {
        int oc = tid & 63, im = tid >> 6;
        float bias = b2[oc];
        float ls = 0.f, lq = 0.f;
        #pragma unroll
        for (int py = 0; py < 4; py++)
            #pragma unroll
            for (int px = 0; px < 4; px++) {
                int r = im * 64 + py * 16 + px * 2;
                float v0 = Ds[r * 65 + oc] + bias;
                float v1 = Ds[(r + 1) * 65 + oc] + bias;
                float v2 = Ds[(r + 8) * 65 + oc] + bias;
                float v3 = Ds[(r + 9) * 65 + oc] + bias;
                ls += v0 + v1 + v2 + v3;
                lq = fmaf(v0, v0, lq); lq = fmaf(v1, v1, lq);
                lq = fmaf(v2, v2, lq); lq = fmaf(v3, v3, lq);
                float mx = fmaxf(fmaxf(v0, v1), fmaxf(v2, v3));
                g_pool2[((size_t)(n0 + im) * 64 + oc) * 16 + py * 4 + px] = mx;
            }
        atomicAdd(&ssum[oc], ls);
        atomicAdd(&ssq[oc], lq);
    }
    __syncthreads();
    if (tid < 64) { atomicAdd(&g_sum2[tid], ssum[tid]); atomicAdd(&g_sq2[tid], ssq[tid]); }
}

// ---------------- fc1 on mma.sync (R10) -------------------------------------
__global__ __launch_bounds__(256) void fc1_mma_kernel(const float* __restrict__ bf1) {
    __shared__ __align__(16) __nv_bfloat16 Ah[128 * 40];
    __shared__ __align__(16) __nv_bfloat16 Al[128 * 40];
    __shared__ __align__(16) __nv_bfloat16 Bs[128 * 40];
    __shared__ float bias_s[128], cs[128], cq[128];
    int tid = threadIdx.x, lane = tid & 31, w = tid >> 5;
    int g = lane >> 2, tig = lane & 3;
    int m0 = blockIdx.x * 128, j0 = blockIdx.y * 128;
    if (tid < 128) { bias_s[tid] = bf1[j0 + tid]; cs[tid] = 0.f; cq[tid] = 0.f; }

    int m_w = (w >> 1) * 32, n_w = (w & 1) * 64;
    float acc[2][8][4];
    #pragma unroll
    for (int mt = 0; mt < 2; mt++)
        #pragma unroll
        for (int nt = 0; nt < 8; nt++)
            #pragma unroll
            for (int q = 0; q < 4; q++) acc[mt][nt][q] = 0.f;

    int row = tid >> 1, half = tid & 1;

    for (int kc = 0; kc < 32; kc++) {
        __syncthreads();
        {
            int oc = kc * 2 + half;
            float sc = g_a2[oc], sd = g_d2[oc];
            const float4* ap4 = (const float4*)(g_pool2 + (size_t)(m0 + row) * 1024 + oc * 16);
            unsigned hw[8], lw[8];
            #pragma unroll
            for (int i = 0; i < 4; i++) {
                float4 r = ap4[i];
                float v0 = fmaxf(fmaf(sc, r.x, sd), 0.f);
                float v1 = fmaxf(fmaf(sc, r.y, sd), 0.f);
                float v2 = fmaxf(fmaf(sc, r.z, sd), 0.f);
                float v3 = fmaxf(fmaf(sc, r.w, sd), 0.f);
                __nv_bfloat162 h01 = __floats2bfloat162_rn(v0, v1);
                __nv_bfloat162 h23 = __floats2bfloat162_rn(v2, v3);
                float2 f01 = __bfloat1622float2(h01);
                float2 f23 = __bfloat1622float2(h23);
                __nv_bfloat162 l01 = __floats2bfloat162_rn(v0 - f01.x, v1 - f01.y);
                __nv_bfloat162 l23 = __floats2bfloat162_rn(v2 - f23.x, v3 - f23.y);
                memcpy(&hw[2 * i], &h01, 4); memcpy(&hw[2 * i + 1], &h23, 4);
                memcpy(&lw[2 * i], &l01, 4); memcpy(&lw[2 * i + 1], &l23, 4);
            }
            unsigned char* da = (unsigned char*)Ah + row * 80 + half * 32;
            *(uint4*)da        = make_uint4(hw[0], hw[1], hw[2], hw[3]);
            *(uint4*)(da + 16) = make_uint4(hw[4], hw[5], hw[6], hw[7]);
            unsigned char* dl = (unsigned char*)Al + row * 80 + half * 32;
            *(uint4*)dl        = make_uint4(lw[0], lw[1], lw[2], lw[3]);
            *(uint4*)(dl + 16) = make_uint4(lw[4], lw[5], lw[6], lw[7]);
        }
        {
            const uint4* bp4 = (const uint4*)(g_qf1b + (size_t)(j0 + row) * 1024 + kc * 32 + half * 16);
            uint4 v0 = bp4[0], v1 = bp4[1];
            unsigned char* d = (unsigned char*)Bs + row * 80 + half * 32;
            *(uint4*)d        = v0;
            *(uint4*)(d + 16) = v1;
        }
        __syncthreads();
        #pragma unroll
        for (int ks = 0; ks < 2; ks++) {
            int kb = (ks * 16 + tig * 2) * 2;
            unsigned b0[8], b1[8];
            #pragma unroll
            for (int nt = 0; nt < 8; nt++) {
                const unsigned char* bp = (const unsigned char*)Bs + (n_w + nt * 8 + g) * 80 + kb;
                b0[nt] = *(const unsigned*)bp;
                b1[nt] = *(const unsigned*)(bp + 16);
            }
            #pragma unroll
            for (int var = 0; var < 2; var++) {
                const unsigned char* Ab = (const unsigned char*)(var ? Al : Ah);
                #pragma unroll
                for (int mt = 0; mt < 2; mt++) {
                    const unsigned char* ap = Ab + (m_w + mt * 16 + g) * 80 + kb;
                    unsigned a0 = *(const unsigned*)ap;
                    unsigned a1 = *(const unsigned*)(ap + 8 * 80);
                    unsigned a2 = *(const unsigned*)(ap + 16);
                    unsigned a3 = *(const unsigned*)(ap + 8 * 80 + 16);
                    #pragma unroll
                    for (int nt = 0; nt < 8; nt++)
                        mma_bf16(acc[mt][nt], a0, a1, a2, a3, b0[nt], b1[nt]);
                }
            }
        }
    }

    #pragma unroll
    for (int mt = 0; mt < 2; mt++) {
        int r0 = m_w + mt * 16 + g;
        size_t gr0 = (size_t)(m0 + r0) * 512 + j0;
        size_t gr1 = (size_t)(m0 + r0 + 8) * 512 + j0;
        #pragma unroll
        for (int nt = 0; nt < 8; nt++) {
            int c0 = n_w + nt * 8 + tig * 2;
            float b0v = bias_s[c0], b1v = bias_s[c0 + 1];
            float v00 = acc[mt][nt][0] + b0v, v01 = acc[mt][nt][1] + b1v;
            float v10 = acc[mt][nt][2] + b0v, v11 = acc[mt][nt][3] + b1v;
            *(float2*)(g_z + gr0 + c0) = make_float2(v00, v01);
            *(float2*)(g_z + gr1 + c0) = make_float2(v10, v11);
            atomicAdd(&cs[c0],     v00 + v10);
            atomicAdd(&cs[c0 + 1], v01 + v11);
            atomicAdd(&cq[c0],     fmaf(v00, v00, v10 * v10));
            atomicAdd(&cq[c0 + 1], fmaf(v01, v01, v11 * v11));
        }
    }
    __syncthreads();
    if (tid < 128) { atomicAdd(&g_sum3[j0 + tid], cs[tid]); atomicAdd(&g_sq3[j0 + tid], cq[tid]); }
}

// ---------------- fc2: [4096,512] x [512,10], one warp per row ----------------
__global__ __launch_bounds__(256) void fc2_kernel(const float* __restrict__ bf2,
                                                  float* __restrict__ out) {
    int w = threadIdx.x >> 5, l = threadIdx.x & 31;
    int row = blockIdx.x * 8 + w;
    const float* zr = g_z + (size_t)row * 512;
    float acc[10];
    #pragma unroll
    for (int k = 0; k < 10; k++) acc[k] = 0.f;
    for (int j = l; j < 512; j += 32) {
        float h = fmaxf(fmaf(g_a3[j], zr[j], g_d3[j]), 0.f);
        #pragma unroll
        for (int k = 0; k < 10; k++) acc[k] = fmaf(h, g_qf2[k * 512 + j], acc[k]);
    }
    #pragma unroll
    for (int k = 0; k < 10; k++)
        #pragma unroll
        for (int o = 16; o; o >>= 1) acc[k] += __shfl_xor_sync(0xffffffffu, acc[k], o);
    if (l < 10) out[row * 10 + l] = acc[l] + bf2[l];
}

// ---------------- host entry ----------------
extern "C" void kernel_launch(void* const* d_in, const int* in_sizes, int n_in,
                              void* d_out, int out_size) {
    const float* x   = (const float*)d_in[0];
    const float* w1  = (const float*)d_in[1];
    const float* b1  = (const float*)d_in[2];
    const float* g1  = (const float*)d_in[3];
    const float* be1 = (const float*)d_in[4];
    const float* w2  = (const float*)d_in[5];
    const float* b2  = (const float*)d_in[6];
    const float* g2  = (const float*)d_in[7];
    const float* be2 = (const float*)d_in[8];
    const float* wf1 = (const float*)d_in[9];
    const float* bf1 = (const float*)d_in[10];
    const float* g3  = (const float*)d_in[11];
    const float* be3 = (const float*)d_in[12];
    const float* wf2 = (const float*)d_in[13];
    const float* bf2 = (const float*)d_in[14];
    float* out = (float*)d_out;

    cudaFuncSetAttribute(conv2_mma_kernel,
                         cudaFuncAttributeMaxDynamicSharedMemorySize, C2_DSM);

    zero_stats_kernel<<<1, 512>>>();

    maxabs_kernel<<<1,   256>>>(w1,  800,    0);
    maxabs_kernel<<<32,  256>>>(w2,  51200,  1);
    maxabs_kernel<<<256, 256>>>(wf1, 524288, 2);
    maxabs_kernel<<<4,   256>>>(wf2, 5120,   3);

    quantize_w1_kernel<<<4, 256>>>(w1);
    quantize_w2_kernel<<<256, 256>>>(w2);
    quantize_kernel<<<2048, 256>>>(wf1, 524288, 2);
    quantize_kernel<<<20,   256>>>(wf2, 5120,   3);

    conv1_mma_kernel<<<NIMG, 256>>>(x, b1);
    finalize_kernel<<<1, 32>>>(g1, be1, 0);

    conv2_mma_kernel<<<NIMG / 2, 256, C2_DSM>>>(b2);
    finalize_kernel<<<1, 64>>>(g2, be2, 1);

    fc1_mma_kernel<<<dim3(32, 4), 256>>>(bf1);
    finalize_kernel<<<2, 256>>>(g3, be3, 2);

    fc2_kernel<<<512, 256>>>(bf2, out);
}